// round 7
// baseline (speedup 1.0000x reference)
#include <cuda_runtime.h>
#include <cstdint>
#include <math.h>

#define L_SEQ   4096
#define DMODEL  256
#define DI      512
#define M_TOT   32768
#define NDBL    144

__device__ float g_xm  [(size_t)M_TOT * DMODEL];
__device__ float g_xpre[(size_t)M_TOT * DI];
__device__ float g_z   [(size_t)M_TOT * DI];
__device__ float g_xc  [(size_t)M_TOT * DI];
__device__ float g_xdbl[(size_t)M_TOT * NDBL];
__device__ float g_dt  [(size_t)M_TOT * DI];
__device__ float g_ygT [(size_t)8 * DI * L_SEQ];   // [b][d][t]
__device__ float g_ym  [(size_t)M_TOT * DMODEL];

__device__ __forceinline__ float warp_sum(float v) {
#pragma unroll
    for (int o = 16; o > 0; o >>= 1) v += __shfl_xor_sync(0xffffffffu, v, o);
    return v;
}

// ---- K1: LN1 + write both direction copies ----
__global__ void k_ln_dup(const float* __restrict__ x,
                         const float* __restrict__ w,
                         const float* __restrict__ b)
{
    int row = blockIdx.x * 8 + (threadIdx.x >> 5);
    int l   = threadIdx.x & 31;
    float a[8], ww[8], bb[8];
    const float* xr = x + (size_t)row * DMODEL + l * 8;
    *(float4*)(a)     = *(const float4*)(xr);
    *(float4*)(a + 4) = *(const float4*)(xr + 4);
    *(float4*)(ww)     = *(const float4*)(w + l * 8);
    *(float4*)(ww + 4) = *(const float4*)(w + l * 8 + 4);
    *(float4*)(bb)     = *(const float4*)(b + l * 8);
    *(float4*)(bb + 4) = *(const float4*)(b + l * 8 + 4);
    float s = 0.f, q = 0.f;
#pragma unroll
    for (int i = 0; i < 8; i++) { s += a[i]; q += a[i] * a[i]; }
    s = warp_sum(s); q = warp_sum(q);
    float mu = s * (1.0f / DMODEL);
    float rs = rsqrtf(q * (1.0f / DMODEL) - mu * mu + 1e-6f);
    float o[8];
#pragma unroll
    for (int i = 0; i < 8; i++) o[i] = (a[i] - mu) * rs * ww[i] + bb[i];

    int bi = row >> 12, ij = row & 4095;
    size_t m1 = (size_t)row;
    size_t m2 = (size_t)(4 + bi) * L_SEQ + ((ij & 63) << 6) + (ij >> 6);
    float* p1 = g_xm + m1 * DMODEL + l * 8;
    float* p2 = g_xm + m2 * DMODEL + l * 8;
    *(float4*)(p1) = *(float4*)(o);  *(float4*)(p1 + 4) = *(float4*)(o + 4);
    *(float4*)(p2) = *(float4*)(o);  *(float4*)(p2 + 4) = *(float4*)(o + 4);
}

// ---- generic fp32 GEMM: C[M,N] = A[M,K] * W[N,K]^T, 128x128x8 tile ----
// MODE 0: A=g_xm (K=256), N=1024 -> split g_xpre/g_z
// MODE 1: A=g_xc (K=512), N=144  -> g_xdbl
// MODE 2: A=g_ygT physically [b][k][t] (K=512), N=256 -> g_ym
template<int MODE>
__global__ void __launch_bounds__(256) k_gemm(const float* __restrict__ Bw)
{
    constexpr int K = (MODE == 0) ? 256 : 512;
    constexpr int N = (MODE == 0) ? 1024 : (MODE == 1) ? 144 : 256;
    const float* __restrict__ A = (MODE == 0) ? g_xm : (MODE == 1) ? g_xc : g_ygT;

    __shared__ float As[8][128];
    __shared__ float Bs[8][128];

    int tid = threadIdx.x;
    int n0 = blockIdx.x * 128, m0 = blockIdx.y * 128;
    int tx = tid & 15, ty = tid >> 4;
    float acc[8][8] = {};

    int arow = tid >> 1, akq = (tid & 1) << 2;   // row-major A loader
    int atk  = tid >> 5, atq = (tid & 31) << 2;  // transposed-physical A loader
    int brow = tid >> 1, bkq = (tid & 1) << 2;

    const float* Aptr = A;
    if (MODE == 2) Aptr = A + (size_t)(m0 >> 12) * DI * L_SEQ + (m0 & 4095);

    for (int k0 = 0; k0 < K; k0 += 8) {
        float4 av;
        if (MODE == 2) av = *(const float4*)&Aptr[(size_t)(k0 + atk) * L_SEQ + atq];
        else           av = *(const float4*)&A[(size_t)(m0 + arow) * K + k0 + akq];
        float4 bv = make_float4(0.f, 0.f, 0.f, 0.f);
        if ((N % 128 == 0) || (n0 + brow < N))
            bv = *(const float4*)&Bw[(size_t)(n0 + brow) * K + k0 + bkq];

        __syncthreads();
        if (MODE == 2) {
            *(float4*)&As[atk][atq] = av;
        } else {
            As[akq + 0][arow] = av.x; As[akq + 1][arow] = av.y;
            As[akq + 2][arow] = av.z; As[akq + 3][arow] = av.w;
        }
        Bs[bkq + 0][brow] = bv.x; Bs[bkq + 1][brow] = bv.y;
        Bs[bkq + 2][brow] = bv.z; Bs[bkq + 3][brow] = bv.w;
        __syncthreads();

#pragma unroll
        for (int kk = 0; kk < 8; kk++) {
            float ra[8], rb[8];
            *(float4*)(ra)     = *(const float4*)&As[kk][ty * 8];
            *(float4*)(ra + 4) = *(const float4*)&As[kk][ty * 8 + 4];
            *(float4*)(rb)     = *(const float4*)&Bs[kk][tx * 8];
            *(float4*)(rb + 4) = *(const float4*)&Bs[kk][tx * 8 + 4];
#pragma unroll
            for (int i = 0; i < 8; i++)
#pragma unroll
                for (int j = 0; j < 8; j++)
                    acc[i][j] = fmaf(ra[i], rb[j], acc[i][j]);
        }
    }

#pragma unroll
    for (int i = 0; i < 8; i++) {
        size_t m = (size_t)m0 + ty * 8 + i;
#pragma unroll
        for (int j = 0; j < 8; j++) {
            int n = n0 + tx * 8 + j;
            float v = acc[i][j];
            if (MODE == 0) {
                if (n < 512) g_xpre[m * DI + n] = v;
                else         g_z   [m * DI + (n - 512)] = v;
            } else if (MODE == 1) {
                if (n < NDBL) g_xdbl[m * NDBL + n] = v;
            } else {
                g_ym[m * DMODEL + n] = v;
            }
        }
    }
}

// ---- K3: depthwise causal conv(4) + SiLU ----
__global__ void k_conv(const float* __restrict__ cw, const float* __restrict__ cb)
{
    int idx = blockIdx.x * 256 + threadIdx.x;     // over M_TOT*DI
    int d = idx & (DI - 1);
    int m = idx >> 9;
    int t = m & (L_SEQ - 1);
    float acc = cb[d];
    float w0 = cw[d*4+0], w1 = cw[d*4+1], w2 = cw[d*4+2], w3 = cw[d*4+3];
    size_t base = (size_t)m * DI + d;
    if (t >= 3) {
        acc = fmaf(g_xpre[base - 3*DI], w0, acc);
        acc = fmaf(g_xpre[base - 2*DI], w1, acc);
        acc = fmaf(g_xpre[base - 1*DI], w2, acc);
    } else {
        if (t >= 2) acc = fmaf(g_xpre[base - 2*DI], w1, acc);
        if (t >= 1) acc = fmaf(g_xpre[base - 1*DI], w2, acc);
    }
    acc = fmaf(g_xpre[base], w3, acc);
    g_xc[base] = acc / (1.0f + __expf(-acc));
}

// ---- K5: dt projection (K=16) + softplus ----
__global__ void k_dt(const float* __restrict__ Wdt, const float* __restrict__ bdt)
{
    __shared__ float sW[16 * 512];   // [r][d]
    __shared__ float sx[16][16];
    int m0 = blockIdx.x * 16;
    int tid = threadIdx.x;
    for (int i = tid; i < 8192; i += 256) {
        int dd = i >> 4, r = i & 15;
        sW[r * 512 + dd] = Wdt[i];
    }
    {
        int mi = tid >> 4, r = tid & 15;
        sx[mi][r] = g_xdbl[(size_t)(m0 + mi) * NDBL + r];
    }
    __syncthreads();
#pragma unroll
    for (int mi = 0; mi < 16; mi++) {
        for (int d = tid; d < 512; d += 256) {
            float acc = bdt[d];
#pragma unroll
            for (int r = 0; r < 16; r++) acc = fmaf(sx[mi][r], sW[r * 512 + d], acc);
            float sp = (acc > 20.f) ? acc : log1pf(__expf(acc));
            g_dt[(size_t)(m0 + mi) * DI + d] = sp;
        }
    }
}

// ---- K6: selective scan + u*D + silu(z) gate, write [b][d][t] ----
__global__ void __launch_bounds__(256) k_scan(const float* __restrict__ A_log,
                                              const float* __restrict__ D_param)
{
    constexpr int CW = 8;
    int b  = blockIdx.y;
    int d0 = blockIdx.x * CW;
    int tid = threadIdx.x, w = tid >> 5, l = tid & 31;
    int d = d0 + w;

    __shared__ float sB[64][68];
    __shared__ float sC[64][68];
    __shared__ float sdt[CW][64];
    __shared__ float su [CW][64];
    __shared__ float sz [CW][64];
    __shared__ float sp4[CW][32][5];

    float A1 = -expf(A_log[d * 64 + l]);
    float A2 = -expf(A_log[d * 64 + 32 + l]);
    float Dp = D_param[d];
    float h1 = 0.f, h2 = 0.f;
    size_t mb = (size_t)b * L_SEQ;
    float* outp = g_ygT + ((size_t)b * DI + d) * L_SEQ;

    for (int t0 = 0; t0 < L_SEQ; t0 += 64) {
        __syncthreads();
        for (int i = tid; i < 64 * 32; i += 256) {
            int row = i >> 5, c4 = (i & 31) << 2;
            float4 v = *(const float4*)&g_xdbl[(mb + t0 + row) * NDBL + 16 + c4];
            if (c4 < 64) *(float4*)&sB[row][c4] = v;
            else         *(float4*)&sC[row][c4 - 64] = v;
        }
        for (int i = tid; i < CW * 64; i += 256) {
            int t = i >> 3, ch = i & 7;
            size_t g = (mb + t0 + t) * DI + d0 + ch;
            sdt[ch][t] = g_dt[g];
            su [ch][t] = g_xc[g];
            sz [ch][t] = g_z [g];
        }
        __syncthreads();

#pragma unroll 4
        for (int t = 0; t < 64; t++) {
            float dtv = sdt[w][t];
            float xx  = dtv * su[w][t];
            float a1 = __expf(dtv * A1);
            float a2 = __expf(dtv * A2);
            h1 = fmaf(a1, h1, xx * sB[t][l]);
            h2 = fmaf(a2, h2, xx * sB[t][l + 32]);
            float p = fmaf(h2, sC[t][l + 32], h1 * sC[t][l]);
            p += __shfl_xor_sync(0xffffffffu, p, 16);
            p += __shfl_xor_sync(0xffffffffu, p, 8);
            p += __shfl_xor_sync(0xffffffffu, p, 4);
            if (l < 4) sp4[w][t & 31][l] = p;
            if ((t & 31) == 31) {
                __syncwarp();
                float q = sp4[w][l][0] + sp4[w][l][1] + sp4[w][l][2] + sp4[w][l][3];
                int tl = (t & 32) + l;
                float zz = sz[w][tl];
                float y = fmaf(su[w][tl], Dp, q) * (zz / (1.0f + __expf(-zz)));
                outp[t0 + tl] = y;
                __syncwarp();
            }
        }
    }
}

// ---- K8: final LN on both halves + residual ----
__global__ void k_final(const float* __restrict__ x,
                        const float* __restrict__ w,
                        const float* __restrict__ b,
                        float* __restrict__ out)
{
    int row = blockIdx.x * 8 + (threadIdx.x >> 5);
    int l   = threadIdx.x & 31;
    int bi = row >> 12, ij = row & 4095;
    size_t m1 = (size_t)row;
    size_t m2 = (size_t)(4 + bi) * L_SEQ + ((ij & 63) << 6) + (ij >> 6);

    float ww[8], bb[8], a[8], c[8], xv[8];
    *(float4*)(ww)     = *(const float4*)(w + l * 8);
    *(float4*)(ww + 4) = *(const float4*)(w + l * 8 + 4);
    *(float4*)(bb)     = *(const float4*)(b + l * 8);
    *(float4*)(bb + 4) = *(const float4*)(b + l * 8 + 4);
    const float* p1 = g_ym + m1 * DMODEL + l * 8;
    const float* p2 = g_ym + m2 * DMODEL + l * 8;
    *(float4*)(a)     = *(const float4*)(p1);
    *(float4*)(a + 4) = *(const float4*)(p1 + 4);
    *(float4*)(c)     = *(const float4*)(p2);
    *(float4*)(c + 4) = *(const float4*)(p2 + 4);
    const float* xr = x + m1 * DMODEL + l * 8;
    *(float4*)(xv)     = *(const float4*)(xr);
    *(float4*)(xv + 4) = *(const float4*)(xr + 4);

    float s1 = 0.f, q1 = 0.f, s2 = 0.f, q2 = 0.f;
#pragma unroll
    for (int i = 0; i < 8; i++) {
        s1 += a[i]; q1 += a[i] * a[i];
        s2 += c[i]; q2 += c[i] * c[i];
    }
    s1 = warp_sum(s1); q1 = warp_sum(q1);
    s2 = warp_sum(s2); q2 = warp_sum(q2);
    float mu1 = s1 * (1.0f / DMODEL);
    float rs1 = rsqrtf(q1 * (1.0f / DMODEL) - mu1 * mu1 + 1e-6f);
    float mu2 = s2 * (1.0f / DMODEL);
    float rs2 = rsqrtf(q2 * (1.0f / DMODEL) - mu2 * mu2 + 1e-6f);

    float o[8];
#pragma unroll
    for (int i = 0; i < 8; i++)
        o[i] = xv[i] + ((a[i] - mu1) * rs1 * ww[i] + bb[i])
                     + ((c[i] - mu2) * rs2 * ww[i] + bb[i]);
    float* op = out + m1 * DMODEL + l * 8;
    *(float4*)(op)     = *(float4*)(o);
    *(float4*)(op + 4) = *(float4*)(o + 4);
}

extern "C" void kernel_launch(void* const* d_in, const int* in_sizes, int n_in,
                              void* d_out, int out_size)
{
    const float* x      = (const float*)d_in[0];
    const float* ln1_w  = (const float*)d_in[1];
    const float* ln1_b  = (const float*)d_in[2];
    const float* ln2_w  = (const float*)d_in[3];
    const float* ln2_b  = (const float*)d_in[4];
    const float* W_in   = (const float*)d_in[5];
    const float* conv_w = (const float*)d_in[6];
    const float* conv_b = (const float*)d_in[7];
    const float* W_x    = (const float*)d_in[8];
    const float* W_dt   = (const float*)d_in[9];
    const float* b_dt   = (const float*)d_in[10];
    const float* A_log  = (const float*)d_in[11];
    const float* D_par  = (const float*)d_in[12];
    const float* W_out  = (const float*)d_in[13];
    float* out = (float*)d_out;

    k_ln_dup<<<2048, 256>>>(x, ln1_w, ln1_b);
    k_gemm<0><<<dim3(8, 256), 256>>>(W_in);
    k_conv<<<65536, 256>>>(conv_w, conv_b);
    k_gemm<1><<<dim3(2, 256), 256>>>(W_x);
    k_dt<<<2048, 256>>>(W_dt, b_dt);
    k_scan<<<dim3(64, 8), 256>>>(A_log, D_par);
    k_gemm<2><<<dim3(2, 256), 256>>>(W_out);
    k_final<<<2048, 256>>>(x, ln2_w, ln2_b, out);
}

// round 10
// speedup vs baseline: 1.3854x; 1.3854x over previous
#include <cuda_runtime.h>
#include <cuda_bf16.h>
#include <cstdint>
#include <math.h>

#define L_SEQ   4096
#define DMODEL  256
#define DI      512
#define M_TOT   32768
#define NDBL    144

typedef __nv_bfloat16 bf16;

// ---------------- scratch ----------------
__device__ bf16  g_xm_hi [(size_t)M_TOT * DMODEL];
__device__ bf16  g_xm_lo [(size_t)M_TOT * DMODEL];
__device__ float g_xpre  [(size_t)M_TOT * DI];
__device__ float g_z     [(size_t)M_TOT * DI];
__device__ float g_xc    [(size_t)M_TOT * DI];
__device__ bf16  g_xc_hi [(size_t)M_TOT * DI];
__device__ bf16  g_xc_lo [(size_t)M_TOT * DI];
__device__ float g_xdbl  [(size_t)M_TOT * NDBL];
__device__ float g_dt    [(size_t)M_TOT * DI];
__device__ float g_ygT   [(size_t)8 * DI * L_SEQ];   // [b][d][t]
__device__ bf16  g_y_hi  [(size_t)M_TOT * DI];       // [m][k]
__device__ bf16  g_y_lo  [(size_t)M_TOT * DI];
__device__ float g_ym    [(size_t)M_TOT * DMODEL];
// weights split to bf16 hi/lo (W_x padded 144 -> 256 rows of zeros)
__device__ bf16  g_wi_hi [1024 * 256];
__device__ bf16  g_wi_lo [1024 * 256];
__device__ bf16  g_wx_hi [256 * 512];
__device__ bf16  g_wx_lo [256 * 512];
__device__ bf16  g_wo_hi [256 * 512];
__device__ bf16  g_wo_lo [256 * 512];

// ---------------- helpers ----------------
__device__ __forceinline__ uint32_t smem_u32(const void* p) {
    uint32_t a;
    asm("{ .reg .u64 t; cvta.to.shared.u64 t, %1; cvt.u32.u64 %0, t; }" : "=r"(a) : "l"(p));
    return a;
}
__device__ __forceinline__ float warp_sum(float v) {
#pragma unroll
    for (int o = 16; o > 0; o >>= 1) v += __shfl_xor_sync(0xffffffffu, v, o);
    return v;
}
__device__ __forceinline__ void split_bf16(float v, bf16& h, bf16& l) {
    h = __float2bfloat16(v);
    l = __float2bfloat16(v - __bfloat162float(h));
}

#define LDSM4(d0, d1, d2, d3, a) \
    asm volatile("ldmatrix.sync.aligned.m8n8.x4.shared.b16 {%0,%1,%2,%3}, [%4];" \
                 : "=r"(d0), "=r"(d1), "=r"(d2), "=r"(d3) : "r"(a))
#define MMA16816(d, a, b0, b1) \
    asm volatile("mma.sync.aligned.m16n8k16.row.col.f32.bf16.bf16.f32 " \
                 "{%0,%1,%2,%3}, {%4,%5,%6,%7}, {%8,%9}, {%0,%1,%2,%3};" \
                 : "+f"((d)[0]), "+f"((d)[1]), "+f"((d)[2]), "+f"((d)[3]) \
                 : "r"((a)[0]), "r"((a)[1]), "r"((a)[2]), "r"((a)[3]), "r"(b0), "r"(b1))

// ---- K1: LN1 + duplicate into bf16 hi/lo (both direction copies) ----
__global__ void k_ln_dup(const float* __restrict__ x,
                         const float* __restrict__ w,
                         const float* __restrict__ b)
{
    int row = blockIdx.x * 8 + (threadIdx.x >> 5);
    int l   = threadIdx.x & 31;
    float a[8], ww[8], bb[8];
    const float* xr = x + (size_t)row * DMODEL + l * 8;
    *(float4*)(a)     = *(const float4*)(xr);
    *(float4*)(a + 4) = *(const float4*)(xr + 4);
    *(float4*)(ww)     = *(const float4*)(w + l * 8);
    *(float4*)(ww + 4) = *(const float4*)(w + l * 8 + 4);
    *(float4*)(bb)     = *(const float4*)(b + l * 8);
    *(float4*)(bb + 4) = *(const float4*)(b + l * 8 + 4);
    float s = 0.f, q = 0.f;
#pragma unroll
    for (int i = 0; i < 8; i++) { s += a[i]; q += a[i] * a[i]; }
    s = warp_sum(s); q = warp_sum(q);
    float mu = s * (1.0f / DMODEL);
    float rs = rsqrtf(q * (1.0f / DMODEL) - mu * mu + 1e-6f);
    bf16 oh[8], ol[8];
#pragma unroll
    for (int i = 0; i < 8; i++) {
        float o = (a[i] - mu) * rs * ww[i] + bb[i];
        split_bf16(o, oh[i], ol[i]);
    }
    int bi = row >> 12, ij = row & 4095;
    size_t m1 = (size_t)row;
    size_t m2 = (size_t)(4 + bi) * L_SEQ + ((ij & 63) << 6) + (ij >> 6);
    *(uint4*)(g_xm_hi + m1 * DMODEL + l * 8) = *(uint4*)oh;
    *(uint4*)(g_xm_lo + m1 * DMODEL + l * 8) = *(uint4*)ol;
    *(uint4*)(g_xm_hi + m2 * DMODEL + l * 8) = *(uint4*)oh;
    *(uint4*)(g_xm_lo + m2 * DMODEL + l * 8) = *(uint4*)ol;
}

// ---- weight split converter (mode selects destination symbol; pads with zeros) ----
__global__ void k_cvt(const float* __restrict__ s, int mode, int nsrc, int ntot)
{
    int i = blockIdx.x * 256 + threadIdx.x;
    if (i >= ntot) return;
    bf16* hi = (mode == 0) ? g_wi_hi : (mode == 1) ? g_wx_hi : g_wo_hi;
    bf16* lo = (mode == 0) ? g_wi_lo : (mode == 1) ? g_wx_lo : g_wo_lo;
    if (i < nsrc) {
        split_bf16(s[i], hi[i], lo[i]);
    } else {
        hi[i] = __float2bfloat16(0.f);
        lo[i] = __float2bfloat16(0.f);
    }
}

// ---------------- HMMA GEMM: C[M,N] = A[M,K] * W[N,K]^T, split bf16 ----------------
// MODE 0: A=g_xm (K=256), N=1024, grid(8,256)  -> split g_xpre/g_z
// MODE 1: A=g_xc (K=512), N=256 (padded), grid(2,256) -> g_xdbl (n<144)
// MODE 2: A=g_y  (K=512), N=256, grid(2,256)  -> g_ym
template<int MODE>
__global__ void __launch_bounds__(256, 1) tg()
{
    constexpr int K   = (MODE == 0) ? 256 : 512;
    constexpr int NKC = K / 32;

    __shared__ bf16 sA[128 * 64];
    __shared__ bf16 sB[128 * 64];

    const bf16* __restrict__ Ahi = (MODE == 0) ? g_xm_hi : (MODE == 1) ? g_xc_hi : g_y_hi;
    const bf16* __restrict__ Alo = (MODE == 0) ? g_xm_lo : (MODE == 1) ? g_xc_lo : g_y_lo;
    const bf16* __restrict__ Bhi = (MODE == 0) ? g_wi_hi : (MODE == 1) ? g_wx_hi : g_wo_hi;
    const bf16* __restrict__ Blo = (MODE == 0) ? g_wi_lo : (MODE == 1) ? g_wx_lo : g_wo_lo;

    int tid = threadIdx.x, w = tid >> 5, lane = tid & 31;
    int m0 = blockIdx.y * 128, n0 = blockIdx.x * 128;
    int wm = (w >> 2) * 64, wn = (w & 3) * 32;

    float acc[4][4][4] = {};

    uint32_t sAu = smem_u32(sA);
    uint32_t sBu = smem_u32(sB);

    // loader precompute: 4 x 16B per thread per tile; i = tid + 256*j
    int lrow[4], lch[4];
#pragma unroll
    for (int j = 0; j < 4; j++) {
        int i = tid + 256 * j;
        lrow[j] = i >> 3;
        lch[j]  = i & 7;
    }

    uint4 pa[4], pb[4];
#define LOADG(kc) { \
    _Pragma("unroll") \
    for (int j = 0; j < 4; j++) { \
        const bf16* asrc = (lch[j] < 4 ? Ahi : Alo) + (size_t)(m0 + lrow[j]) * K + (kc) * 32 + (lch[j] & 3) * 8; \
        const bf16* bsrc = (lch[j] < 4 ? Bhi : Blo) + (size_t)(n0 + lrow[j]) * K + (kc) * 32 + (lch[j] & 3) * 8; \
        pa[j] = *(const uint4*)asrc; \
        pb[j] = *(const uint4*)bsrc; \
    } }
#define STORES() { \
    _Pragma("unroll") \
    for (int j = 0; j < 4; j++) { \
        int off = lrow[j] * 64 + ((lch[j] ^ (lrow[j] & 7)) << 3); \
        *(uint4*)&sA[off] = pa[j]; \
        *(uint4*)&sB[off] = pb[j]; \
    } }

    LOADG(0); STORES();
    __syncthreads();

    int q8 = lane >> 3, r8 = lane & 7;

    for (int kc = 0; kc < NKC; kc++) {
        if (kc + 1 < NKC) LOADG(kc + 1);

#pragma unroll
        for (int ks = 0; ks < 2; ks++) {
            int ckh = ks * 2;        // hi chunks
            int ckl = 4 + ks * 2;    // lo chunks
            uint32_t ah[4][4], al[4][4], bh[2][4], bl[2][4];
            // A fragments: m-tile mt, quad q8: rows wm+mt*16 + (q8&1)*8 + r8, chunk ck + (q8>>1)
#pragma unroll
            for (int mt = 0; mt < 4; mt++) {
                int row = wm + mt * 16 + ((q8 & 1) << 3) + r8;
                int c  = ckh + (q8 >> 1);
                uint32_t a1 = sAu + (row * 64 + ((c ^ (row & 7)) << 3)) * 2;
                LDSM4(ah[mt][0], ah[mt][1], ah[mt][2], ah[mt][3], a1);
                int c2 = ckl + (q8 >> 1);
                uint32_t a2 = sAu + (row * 64 + ((c2 ^ (row & 7)) << 3)) * 2;
                LDSM4(al[mt][0], al[mt][1], al[mt][2], al[mt][3], a2);
            }
            // B fragments: pair p covers n-tiles 2p, 2p+1: rows wn + p*16 + (q8>>1)*8 + r8, chunk ck + (q8&1)
#pragma unroll
            for (int p = 0; p < 2; p++) {
                int row = wn + p * 16 + ((q8 >> 1) << 3) + r8;
                int c  = ckh + (q8 & 1);
                uint32_t a1 = sBu + (row * 64 + ((c ^ (row & 7)) << 3)) * 2;
                LDSM4(bh[p][0], bh[p][1], bh[p][2], bh[p][3], a1);
                int c2 = ckl + (q8 & 1);
                uint32_t a2 = sBu + (row * 64 + ((c2 ^ (row & 7)) << 3)) * 2;
                LDSM4(bl[p][0], bl[p][1], bl[p][2], bl[p][3], a2);
            }
#pragma unroll
            for (int mt = 0; mt < 4; mt++) {
#pragma unroll
                for (int nt = 0; nt < 4; nt++) {
                    int p = nt >> 1, o = (nt & 1) << 1;
                    MMA16816(acc[mt][nt], ah[mt], bh[p][o], bh[p][o + 1]);   // hi*hi
                    MMA16816(acc[mt][nt], ah[mt], bl[p][o], bl[p][o + 1]);   // hi*lo
                    MMA16816(acc[mt][nt], al[mt], bh[p][o], bh[p][o + 1]);   // lo*hi
                }
            }
        }

        __syncthreads();
        if (kc + 1 < NKC) {
            STORES();
            __syncthreads();
        }
    }

    // ---- epilogue: direct register -> gmem ----
    int g = lane >> 2, qq = lane & 3;
#pragma unroll
    for (int mt = 0; mt < 4; mt++) {
#pragma unroll
        for (int nt = 0; nt < 4; nt++) {
            int col = n0 + wn + nt * 8 + qq * 2;
            size_t r0 = (size_t)m0 + wm + mt * 16 + g;
#pragma unroll
            for (int hrow = 0; hrow < 2; hrow++) {
                size_t m = r0 + hrow * 8;
                float2 v = make_float2(acc[mt][nt][hrow * 2], acc[mt][nt][hrow * 2 + 1]);
                if (MODE == 0) {
                    if (col < 512) *(float2*)&g_xpre[m * DI + col] = v;
                    else           *(float2*)&g_z   [m * DI + col - 512] = v;
                } else if (MODE == 1) {
                    if (col < NDBL) *(float2*)&g_xdbl[m * NDBL + col] = v;
                } else {
                    *(float2*)&g_ym[m * DMODEL + col] = v;
                }
            }
        }
    }
}

// ---- K3: depthwise causal conv(4) + SiLU (+ bf16 hi/lo for GEMM2) ----
__global__ void k_conv(const float* __restrict__ cw, const float* __restrict__ cb)
{
    int idx = blockIdx.x * 256 + threadIdx.x;
    int d = idx & (DI - 1);
    int m = idx >> 9;
    int t = m & (L_SEQ - 1);
    float acc = cb[d];
    float w0 = cw[d*4+0], w1 = cw[d*4+1], w2 = cw[d*4+2], w3 = cw[d*4+3];
    size_t base = (size_t)m * DI + d;
    if (t >= 3) {
        acc = fmaf(g_xpre[base - 3*DI], w0, acc);
        acc = fmaf(g_xpre[base - 2*DI], w1, acc);
        acc = fmaf(g_xpre[base - 1*DI], w2, acc);
    } else {
        if (t >= 2) acc = fmaf(g_xpre[base - 2*DI], w1, acc);
        if (t >= 1) acc = fmaf(g_xpre[base - 1*DI], w2, acc);
    }
    acc = fmaf(g_xpre[base], w3, acc);
    float v = acc / (1.0f + __expf(-acc));
    g_xc[base] = v;
    bf16 h, l; split_bf16(v, h, l);
    g_xc_hi[base] = h;
    g_xc_lo[base] = l;
}

// ---- K5: dt projection (K=16) + softplus ----
__global__ void k_dt(const float* __restrict__ Wdt, const float* __restrict__ bdt)
{
    __shared__ float sW[16 * 512];
    __shared__ float sx[16][16];
    int m0 = blockIdx.x * 16;
    int tid = threadIdx.x;
    for (int i = tid; i < 8192; i += 256) {
        int dd = i >> 4, r = i & 15;
        sW[r * 512 + dd] = Wdt[i];
    }
    {
        int mi = tid >> 4, r = tid & 15;
        sx[mi][r] = g_xdbl[(size_t)(m0 + mi) * NDBL + r];
    }
    __syncthreads();
#pragma unroll
    for (int mi = 0; mi < 16; mi++) {
        for (int d = tid; d < 512; d += 256) {
            float acc = bdt[d];
#pragma unroll
            for (int r = 0; r < 16; r++) acc = fmaf(sx[mi][r], sW[r * 512 + d], acc);
            float sp = (acc > 20.f) ? acc : log1pf(__expf(acc));
            g_dt[(size_t)(m0 + mi) * DI + d] = sp;
        }
    }
}

// ---- K6: selective scan + u*D + silu(z) gate, write [b][d][t] ----
__global__ void __launch_bounds__(256) k_scan(const float* __restrict__ A_log,
                                              const float* __restrict__ D_param)
{
    constexpr int CW = 8;
    int b  = blockIdx.y;
    int d0 = blockIdx.x * CW;
    int tid = threadIdx.x, w = tid >> 5, l = tid & 31;
    int d = d0 + w;

    __shared__ float sB[64][68];
    __shared__ float sC[64][68];
    __shared__ float sdt[CW][64];
    __shared__ float su [CW][64];
    __shared__ float sz [CW][64];
    __shared__ float sp4[CW][32][5];

    float A1 = -expf(A_log[d * 64 + l]);
    float A2 = -expf(A_log[d * 64 + 32 + l]);
    float Dp = D_param[d];
    float h1 = 0.f, h2 = 0.f;
    size_t mb = (size_t)b * L_SEQ;
    float* outp = g_ygT + ((size_t)b * DI + d) * L_SEQ;

    for (int t0 = 0; t0 < L_SEQ; t0 += 64) {
        __syncthreads();
        for (int i = tid; i < 64 * 32; i += 256) {
            int row = i >> 5, c4 = (i & 31) << 2;
            float4 v = *(const float4*)&g_xdbl[(mb + t0 + row) * NDBL + 16 + c4];
            if (c4 < 64) *(float4*)&sB[row][c4] = v;
            else         *(float4*)&sC[row][c4 - 64] = v;
        }
        for (int i = tid; i < CW * 64; i += 256) {
            int t = i >> 3, ch = i & 7;
            size_t g = (mb + t0 + t) * DI + d0 + ch;
            sdt[ch][t] = g_dt[g];
            su [ch][t] = g_xc[g];
            sz [ch][t] = g_z [g];
        }
        __syncthreads();

#pragma unroll 4
        for (int t = 0; t < 64; t++) {
            float dtv = sdt[w][t];
            float xx  = dtv * su[w][t];
            float a1 = __expf(dtv * A1);
            float a2 = __expf(dtv * A2);
            h1 = fmaf(a1, h1, xx * sB[t][l]);
            h2 = fmaf(a2, h2, xx * sB[t][l + 32]);
            float p = fmaf(h2, sC[t][l + 32], h1 * sC[t][l]);
            p += __shfl_xor_sync(0xffffffffu, p, 16);
            p += __shfl_xor_sync(0xffffffffu, p, 8);
            p += __shfl_xor_sync(0xffffffffu, p, 4);
            if (l < 4) sp4[w][t & 31][l] = p;
            if ((t & 31) == 31) {
                __syncwarp();
                float q = sp4[w][l][0] + sp4[w][l][1] + sp4[w][l][2] + sp4[w][l][3];
                int tl = (t & 32) + l;
                float zz = sz[w][tl];
                float y = fmaf(su[w][tl], Dp, q) * (zz / (1.0f + __expf(-zz)));
                outp[t0 + tl] = y;
                __syncwarp();
            }
        }
    }
}

// ---- K7: transpose y [b][d][t] -> [m][k] bf16 hi/lo ----
__global__ void k_ytr()
{
    __shared__ float s[32][33];
    int t0 = blockIdx.x * 32, d0 = blockIdx.y * 32, b = blockIdx.z;
    int tx = threadIdx.x, ty = threadIdx.y;   // (32,8)
    for (int r = ty; r < 32; r += 8)
        s[r][tx] = g_ygT[((size_t)b * DI + d0 + r) * L_SEQ + t0 + tx];
    __syncthreads();
    for (int r = ty; r < 32; r += 8) {
        size_t m = (size_t)b * L_SEQ + t0 + r;
        float v = s[tx][r];
        bf16 h, l; split_bf16(v, h, l);
        g_y_hi[m * DI + d0 + tx] = h;
        g_y_lo[m * DI + d0 + tx] = l;
    }
}

// ---- K8: final LN on both halves + residual ----
__global__ void k_final(const float* __restrict__ x,
                        const float* __restrict__ w,
                        const float* __restrict__ b,
                        float* __restrict__ out)
{
    int row = blockIdx.x * 8 + (threadIdx.x >> 5);
    int l   = threadIdx.x & 31;
    int bi = row >> 12, ij = row & 4095;
    size_t m1 = (size_t)row;
    size_t m2 = (size_t)(4 + bi) * L_SEQ + ((ij & 63) << 6) + (ij >> 6);

    float ww[8], bb[8], a[8], c[8], xv[8];
    *(float4*)(ww)     = *(const float4*)(w + l * 8);
    *(float4*)(ww + 4) = *(const float4*)(w + l * 8 + 4);
    *(float4*)(bb)     = *(const float4*)(b + l * 8);
    *(float4*)(bb + 4) = *(const float4*)(b + l * 8 + 4);
    const float* p1 = g_ym + m1 * DMODEL + l * 8;
    const float* p2 = g_ym + m2 * DMODEL + l * 8;
    *(float4*)(a)     = *(const float4*)(p1);
    *(float4*)(a + 4) = *(const float4*)(p1 + 4);
    *(float4*)(c)     = *(const float4*)(p2);
    *(float4*)(c + 4) = *(const float4*)(p2 + 4);
    const float* xr = x + m1 * DMODEL + l * 8;
    *(float4*)(xv)     = *(const float4*)(xr);
    *(float4*)(xv + 4) = *(const float4*)(xr + 4);

    float s1 = 0.f, q1 = 0.f, s2 = 0.f, q2 = 0.f;
#pragma unroll
    for (int i = 0; i < 8; i++) {
        s1 += a[i]; q1 += a[i] * a[i];
        s2 += c[i]; q2 += c[i] * c[i];
    }
    s1 = warp_sum(s1); q1 = warp_sum(q1);
    s2 = warp_sum(s2); q2 = warp_sum(q2);
    float mu1 = s1 * (1.0f / DMODEL);
    float rs1 = rsqrtf(q1 * (1.0f / DMODEL) - mu1 * mu1 + 1e-6f);
    float mu2 = s2 * (1.0f / DMODEL);
    float rs2 = rsqrtf(q2 * (1.0f / DMODEL) - mu2 * mu2 + 1e-6f);

    float o[8];
#pragma unroll
    for (int i = 0; i < 8; i++)
        o[i] = xv[i] + ((a[i] - mu1) * rs1 * ww[i] + bb[i])
                     + ((c[i] - mu2) * rs2 * ww[i] + bb[i]);
    float* op = out + m1 * DMODEL + l * 8;
    *(float4*)(op)     = *(float4*)(o);
    *(float4*)(op + 4) = *(float4*)(o + 4);
}

extern "C" void kernel_launch(void* const* d_in, const int* in_sizes, int n_in,
                              void* d_out, int out_size)
{
    const float* x      = (const float*)d_in[0];
    const float* ln1_w  = (const float*)d_in[1];
    const float* ln1_b  = (const float*)d_in[2];
    const float* ln2_w  = (const float*)d_in[3];
    const float* ln2_b  = (const float*)d_in[4];
    const float* W_in   = (const float*)d_in[5];
    const float* conv_w = (const float*)d_in[6];
    const float* conv_b = (const float*)d_in[7];
    const float* W_x    = (const float*)d_in[8];
    const float* W_dt   = (const float*)d_in[9];
    const float* b_dt   = (const float*)d_in[10];
    const float* A_log  = (const float*)d_in[11];
    const float* D_par  = (const float*)d_in[12];
    const float* W_out  = (const float*)d_in[13];
    float* out = (float*)d_out;

    k_ln_dup<<<2048, 256>>>(x, ln1_w, ln1_b);
    k_cvt<<<1024, 256>>>(W_in,  0, 1024 * 256, 1024 * 256);
    k_cvt<<<512,  256>>>(W_x,   1, 144 * 512,  256 * 512);
    k_cvt<<<512,  256>>>(W_out, 2, 256 * 512,  256 * 512);
    tg<0><<<dim3(8, 256), 256>>>();
    k_conv<<<65536, 256>>>(conv_w, conv_b);
    tg<1><<<dim3(2, 256), 256>>>();
    k_dt<<<2048, 256>>>(W_dt, b_dt);
    k_scan<<<dim3(64, 8), 256>>>(A_log, D_par);
    k_ytr<<<dim3(128, 16, 8), dim3(32, 8)>>>();
    tg<2><<<dim3(2, 256), 256>>>();
    k_final<<<2048, 256>>>(x, ln2_w, ln2_b, out);
}

// round 11
// speedup vs baseline: 1.4536x; 1.0492x over previous
#include <cuda_runtime.h>
#include <cuda_bf16.h>
#include <cstdint>
#include <math.h>

#define L_SEQ   4096
#define DMODEL  256
#define DI      512
#define M_TOT   32768
#define NDBL    144

typedef __nv_bfloat16 bf16;

// ---------------- scratch ----------------
__device__ bf16  g_xm_hi [(size_t)M_TOT * DMODEL];
__device__ bf16  g_xm_lo [(size_t)M_TOT * DMODEL];
__device__ float g_xpre  [(size_t)M_TOT * DI];
__device__ float g_z     [(size_t)M_TOT * DI];
__device__ float g_xc    [(size_t)M_TOT * DI];
__device__ bf16  g_xc_hi [(size_t)M_TOT * DI];
__device__ bf16  g_xc_lo [(size_t)M_TOT * DI];
__device__ float g_xdbl  [(size_t)M_TOT * NDBL];
__device__ float g_dt    [(size_t)M_TOT * DI];
__device__ float g_ygT   [(size_t)8 * DI * L_SEQ];   // [b][d][t]
__device__ bf16  g_y_hi  [(size_t)M_TOT * DI];       // [m][k]
__device__ bf16  g_y_lo  [(size_t)M_TOT * DI];
__device__ float g_ym    [(size_t)M_TOT * DMODEL];
// weights split to bf16 hi/lo (W_x padded 144 -> 256 rows of zeros)
__device__ bf16  g_wi_hi [1024 * 256];
__device__ bf16  g_wi_lo [1024 * 256];
__device__ bf16  g_wx_hi [256 * 512];
__device__ bf16  g_wx_lo [256 * 512];
__device__ bf16  g_wo_hi [256 * 512];
__device__ bf16  g_wo_lo [256 * 512];

// ---------------- helpers ----------------
__device__ __forceinline__ uint32_t smem_u32(const void* p) {
    uint32_t a;
    asm("{ .reg .u64 t; cvta.to.shared.u64 t, %1; cvt.u32.u64 %0, t; }" : "=r"(a) : "l"(p));
    return a;
}
__device__ __forceinline__ float warp_sum(float v) {
#pragma unroll
    for (int o = 16; o > 0; o >>= 1) v += __shfl_xor_sync(0xffffffffu, v, o);
    return v;
}
__device__ __forceinline__ void split_bf16(float v, bf16& h, bf16& l) {
    h = __float2bfloat16(v);
    l = __float2bfloat16(v - __bfloat162float(h));
}

#define LDSM4(d0, d1, d2, d3, a) \
    asm volatile("ldmatrix.sync.aligned.m8n8.x4.shared.b16 {%0,%1,%2,%3}, [%4];" \
                 : "=r"(d0), "=r"(d1), "=r"(d2), "=r"(d3) : "r"(a))
#define MMA16816(d, a, b0, b1) \
    asm volatile("mma.sync.aligned.m16n8k16.row.col.f32.bf16.bf16.f32 " \
                 "{%0,%1,%2,%3}, {%4,%5,%6,%7}, {%8,%9}, {%0,%1,%2,%3};" \
                 : "+f"((d)[0]), "+f"((d)[1]), "+f"((d)[2]), "+f"((d)[3]) \
                 : "r"((a)[0]), "r"((a)[1]), "r"((a)[2]), "r"((a)[3]), "r"(b0), "r"(b1))
#define CPA(dst, src) \
    asm volatile("cp.async.cg.shared.global [%0], [%1], 16;" :: "r"(dst), "l"(src))
#define CP_COMMIT() asm volatile("cp.async.commit_group;" ::: "memory")
#define CP_WAIT1()  asm volatile("cp.async.wait_group 1;" ::: "memory")
#define CP_WAIT0()  asm volatile("cp.async.wait_group 0;" ::: "memory")

// ---- K1: LN1 + duplicate into bf16 hi/lo (both direction copies) ----
__global__ void k_ln_dup(const float* __restrict__ x,
                         const float* __restrict__ w,
                         const float* __restrict__ b)
{
    int row = blockIdx.x * 8 + (threadIdx.x >> 5);
    int l   = threadIdx.x & 31;
    float a[8], ww[8], bb[8];
    const float* xr = x + (size_t)row * DMODEL + l * 8;
    *(float4*)(a)     = *(const float4*)(xr);
    *(float4*)(a + 4) = *(const float4*)(xr + 4);
    *(float4*)(ww)     = *(const float4*)(w + l * 8);
    *(float4*)(ww + 4) = *(const float4*)(w + l * 8 + 4);
    *(float4*)(bb)     = *(const float4*)(b + l * 8);
    *(float4*)(bb + 4) = *(const float4*)(b + l * 8 + 4);
    float s = 0.f, q = 0.f;
#pragma unroll
    for (int i = 0; i < 8; i++) { s += a[i]; q += a[i] * a[i]; }
    s = warp_sum(s); q = warp_sum(q);
    float mu = s * (1.0f / DMODEL);
    float rs = rsqrtf(q * (1.0f / DMODEL) - mu * mu + 1e-6f);
    bf16 oh[8], ol[8];
#pragma unroll
    for (int i = 0; i < 8; i++) {
        float o = (a[i] - mu) * rs * ww[i] + bb[i];
        split_bf16(o, oh[i], ol[i]);
    }
    int bi = row >> 12, ij = row & 4095;
    size_t m1 = (size_t)row;
    size_t m2 = (size_t)(4 + bi) * L_SEQ + ((ij & 63) << 6) + (ij >> 6);
    *(uint4*)(g_xm_hi + m1 * DMODEL + l * 8) = *(uint4*)oh;
    *(uint4*)(g_xm_lo + m1 * DMODEL + l * 8) = *(uint4*)ol;
    *(uint4*)(g_xm_hi + m2 * DMODEL + l * 8) = *(uint4*)oh;
    *(uint4*)(g_xm_lo + m2 * DMODEL + l * 8) = *(uint4*)ol;
}

// ---- weight split converter (mode selects destination symbol; pads with zeros) ----
__global__ void k_cvt(const float* __restrict__ s, int mode, int nsrc, int ntot)
{
    int i = blockIdx.x * 256 + threadIdx.x;
    if (i >= ntot) return;
    bf16* hi = (mode == 0) ? g_wi_hi : (mode == 1) ? g_wx_hi : g_wo_hi;
    bf16* lo = (mode == 0) ? g_wi_lo : (mode == 1) ? g_wx_lo : g_wo_lo;
    if (i < nsrc) {
        split_bf16(s[i], hi[i], lo[i]);
    } else {
        hi[i] = __float2bfloat16(0.f);
        lo[i] = __float2bfloat16(0.f);
    }
}

// ---------------- HMMA GEMM: C[M,N] = A[M,K] * W[N,K]^T, split bf16 ----------------
// 2-stage cp.async double-buffered pipeline. Dynamic smem: 2 stages x (A 16KB + B 16KB) = 64KB.
// MODE 0: A=g_xm (K=256), N=1024, grid(8,256)  -> split g_xpre/g_z
// MODE 1: A=g_xc (K=512), N=256 (padded), grid(2,256) -> g_xdbl (n<144)
// MODE 2: A=g_y  (K=512), N=256, grid(2,256)  -> g_ym
template<int MODE>
__global__ void __launch_bounds__(256, 2) tg()
{
    constexpr int K   = (MODE == 0) ? 256 : 512;
    constexpr int NKC = K / 32;

    extern __shared__ bf16 smem[];

    const bf16* __restrict__ Ahi = (MODE == 0) ? g_xm_hi : (MODE == 1) ? g_xc_hi : g_y_hi;
    const bf16* __restrict__ Alo = (MODE == 0) ? g_xm_lo : (MODE == 1) ? g_xc_lo : g_y_lo;
    const bf16* __restrict__ Bhi = (MODE == 0) ? g_wi_hi : (MODE == 1) ? g_wx_hi : g_wo_hi;
    const bf16* __restrict__ Blo = (MODE == 0) ? g_wi_lo : (MODE == 1) ? g_wx_lo : g_wo_lo;

    int tid = threadIdx.x, w = tid >> 5, lane = tid & 31;
    int m0 = blockIdx.y * 128, n0 = blockIdx.x * 128;
    int wm = (w >> 2) * 64, wn = (w & 3) * 32;

    float acc[4][4][4] = {};

    uint32_t sbase = smem_u32(smem);

    // loader indices: 4 x (A 16B + B 16B) per thread per stage
    int lrow[4], lch[4];
#pragma unroll
    for (int j = 0; j < 4; j++) {
        int i = tid + 256 * j;
        lrow[j] = i >> 3;
        lch[j]  = i & 7;
    }

#define LOADS(s, kc) { \
    uint32_t abase = sbase + (uint32_t)(s) * 32768u; \
    _Pragma("unroll") \
    for (int j = 0; j < 4; j++) { \
        const bf16* asrc = (lch[j] < 4 ? Ahi : Alo) + (size_t)(m0 + lrow[j]) * K + (kc) * 32 + (lch[j] & 3) * 8; \
        const bf16* bsrc = (lch[j] < 4 ? Bhi : Blo) + (size_t)(n0 + lrow[j]) * K + (kc) * 32 + (lch[j] & 3) * 8; \
        uint32_t off = 2u * (uint32_t)(lrow[j] * 64 + ((lch[j] ^ (lrow[j] & 7)) << 3)); \
        CPA(abase + off, asrc); \
        CPA(abase + 16384u + off, bsrc); \
    } }

    LOADS(0, 0); CP_COMMIT();

    int q8 = lane >> 3, r8 = lane & 7;

    for (int kc = 0; kc < NKC; kc++) {
        int cur = kc & 1;
        if (kc + 1 < NKC) {
            LOADS(cur ^ 1, kc + 1); CP_COMMIT();
            CP_WAIT1();
        } else {
            CP_WAIT0();
        }
        __syncthreads();

        uint32_t sAu = sbase + (uint32_t)cur * 32768u;
        uint32_t sBu = sAu + 16384u;

#pragma unroll
        for (int ks = 0; ks < 2; ks++) {
            int ckh = ks * 2;        // hi chunks
            int ckl = 4 + ks * 2;    // lo chunks
            uint32_t ah[4][4], al[4][4], bh[2][4], bl[2][4];
            // A fragments: m-tile mt, quad q8: rows wm+mt*16 + (q8&1)*8 + r8, chunk ck + (q8>>1)
#pragma unroll
            for (int mt = 0; mt < 4; mt++) {
                int row = wm + mt * 16 + ((q8 & 1) << 3) + r8;
                int c  = ckh + (q8 >> 1);
                uint32_t a1 = sAu + (row * 64 + ((c ^ (row & 7)) << 3)) * 2;
                LDSM4(ah[mt][0], ah[mt][1], ah[mt][2], ah[mt][3], a1);
                int c2 = ckl + (q8 >> 1);
                uint32_t a2 = sAu + (row * 64 + ((c2 ^ (row & 7)) << 3)) * 2;
                LDSM4(al[mt][0], al[mt][1], al[mt][2], al[mt][3], a2);
            }
            // B fragments: pair p covers n-tiles 2p, 2p+1: rows wn + p*16 + (q8>>1)*8 + r8, chunk ck + (q8&1)
#pragma unroll
            for (int p = 0; p < 2; p++) {
                int row = wn + p * 16 + ((q8 >> 1) << 3) + r8;
                int c  = ckh + (q8 & 1);
                uint32_t a1 = sBu + (row * 64 + ((c ^ (row & 7)) << 3)) * 2;
                LDSM4(bh[p][0], bh[p][1], bh[p][2], bh[p][3], a1);
                int c2 = ckl + (q8 & 1);
                uint32_t a2 = sBu + (row * 64 + ((c2 ^ (row & 7)) << 3)) * 2;
                LDSM4(bl[p][0], bl[p][1], bl[p][2], bl[p][3], a2);
            }
#pragma unroll
            for (int mt = 0; mt < 4; mt++) {
#pragma unroll
                for (int nt = 0; nt < 4; nt++) {
                    int p = nt >> 1, o = (nt & 1) << 1;
                    MMA16816(acc[mt][nt], ah[mt], bh[p][o], bh[p][o + 1]);   // hi*hi
                    MMA16816(acc[mt][nt], ah[mt], bl[p][o], bl[p][o + 1]);   // hi*lo
                    MMA16816(acc[mt][nt], al[mt], bh[p][o], bh[p][o + 1]);   // lo*hi
                }
            }
        }

        __syncthreads();
    }

    // ---- epilogue: direct register -> gmem ----
    int g = lane >> 2, qq = lane & 3;
#pragma unroll
    for (int mt = 0; mt < 4; mt++) {
#pragma unroll
        for (int nt = 0; nt < 4; nt++) {
            int col = n0 + wn + nt * 8 + qq * 2;
            size_t r0 = (size_t)m0 + wm + mt * 16 + g;
#pragma unroll
            for (int hrow = 0; hrow < 2; hrow++) {
                size_t m = r0 + hrow * 8;
                float2 v = make_float2(acc[mt][nt][hrow * 2], acc[mt][nt][hrow * 2 + 1]);
                if (MODE == 0) {
                    if (col < 512) *(float2*)&g_xpre[m * DI + col] = v;
                    else           *(float2*)&g_z   [m * DI + col - 512] = v;
                } else if (MODE == 1) {
                    if (col < NDBL) *(float2*)&g_xdbl[m * NDBL + col] = v;
                } else {
                    *(float2*)&g_ym[m * DMODEL + col] = v;
                }
            }
        }
    }
}

// ---- K3: depthwise causal conv(4) + SiLU (+ bf16 hi/lo for GEMM2) ----
__global__ void k_conv(const float* __restrict__ cw, const float* __restrict__ cb)
{
    int idx = blockIdx.x * 256 + threadIdx.x;
    int d = idx & (DI - 1);
    int m = idx >> 9;
    int t = m & (L_SEQ - 1);
    float acc = cb[d];
    float w0 = cw[d*4+0], w1 = cw[d*4+1], w2 = cw[d*4+2], w3 = cw[d*4+3];
    size_t base = (size_t)m * DI + d;
    if (t >= 3) {
        acc = fmaf(g_xpre[base - 3*DI], w0, acc);
        acc = fmaf(g_xpre[base - 2*DI], w1, acc);
        acc = fmaf(g_xpre[base - 1*DI], w2, acc);
    } else {
        if (t >= 2) acc = fmaf(g_xpre[base - 2*DI], w1, acc);
        if (t >= 1) acc = fmaf(g_xpre[base - 1*DI], w2, acc);
    }
    acc = fmaf(g_xpre[base], w3, acc);
    float v = acc / (1.0f + __expf(-acc));
    g_xc[base] = v;
    bf16 h, l; split_bf16(v, h, l);
    g_xc_hi[base] = h;
    g_xc_lo[base] = l;
}

// ---- K5: dt projection (K=16) + softplus ----
__global__ void k_dt(const float* __restrict__ Wdt, const float* __restrict__ bdt)
{
    __shared__ float sW[16 * 512];
    __shared__ float sx[16][16];
    int m0 = blockIdx.x * 16;
    int tid = threadIdx.x;
    for (int i = tid; i < 8192; i += 256) {
        int dd = i >> 4, r = i & 15;
        sW[r * 512 + dd] = Wdt[i];
    }
    {
        int mi = tid >> 4, r = tid & 15;
        sx[mi][r] = g_xdbl[(size_t)(m0 + mi) * NDBL + r];
    }
    __syncthreads();
#pragma unroll
    for (int mi = 0; mi < 16; mi++) {
        for (int d = tid; d < 512; d += 256) {
            float acc = bdt[d];
#pragma unroll
            for (int r = 0; r < 16; r++) acc = fmaf(sx[mi][r], sW[r * 512 + d], acc);
            float sp = (acc > 20.f) ? acc : log1pf(__expf(acc));
            g_dt[(size_t)(m0 + mi) * DI + d] = sp;
        }
    }
}

// ---- K6: selective scan + u*D + silu(z) gate, write [b][d][t] ----
__global__ void __launch_bounds__(256) k_scan(const float* __restrict__ A_log,
                                              const float* __restrict__ D_param)
{
    constexpr int CW = 8;
    int b  = blockIdx.y;
    int d0 = blockIdx.x * CW;
    int tid = threadIdx.x, w = tid >> 5, l = tid & 31;
    int d = d0 + w;

    __shared__ float sB[64][68];
    __shared__ float sC[64][68];
    __shared__ float sdt[CW][64];
    __shared__ float su [CW][64];
    __shared__ float sz [CW][64];
    __shared__ float sp4[CW][32][5];

    float A1 = -expf(A_log[d * 64 + l]);
    float A2 = -expf(A_log[d * 64 + 32 + l]);
    float Dp = D_param[d];
    float h1 = 0.f, h2 = 0.f;
    size_t mb = (size_t)b * L_SEQ;
    float* outp = g_ygT + ((size_t)b * DI + d) * L_SEQ;

    for (int t0 = 0; t0 < L_SEQ; t0 += 64) {
        __syncthreads();
        for (int i = tid; i < 64 * 32; i += 256) {
            int row = i >> 5, c4 = (i & 31) << 2;
            float4 v = *(const float4*)&g_xdbl[(mb + t0 + row) * NDBL + 16 + c4];
            if (c4 < 64) *(float4*)&sB[row][c4] = v;
            else         *(float4*)&sC[row][c4 - 64] = v;
        }
        for (int i = tid; i < CW * 64; i += 256) {
            int t = i >> 3, ch = i & 7;
            size_t g = (mb + t0 + t) * DI + d0 + ch;
            sdt[ch][t] = g_dt[g];
            su [ch][t] = g_xc[g];
            sz [ch][t] = g_z [g];
        }
        __syncthreads();

#pragma unroll 4
        for (int t = 0; t < 64; t++) {
            float dtv = sdt[w][t];
            float xx  = dtv * su[w][t];
            float a1 = __expf(dtv * A1);
            float a2 = __expf(dtv * A2);
            h1 = fmaf(a1, h1, xx * sB[t][l]);
            h2 = fmaf(a2, h2, xx * sB[t][l + 32]);
            float p = fmaf(h2, sC[t][l + 32], h1 * sC[t][l]);
            p += __shfl_xor_sync(0xffffffffu, p, 16);
            p += __shfl_xor_sync(0xffffffffu, p, 8);
            p += __shfl_xor_sync(0xffffffffu, p, 4);
            if (l < 4) sp4[w][t & 31][l] = p;
            if ((t & 31) == 31) {
                __syncwarp();
                float q = sp4[w][l][0] + sp4[w][l][1] + sp4[w][l][2] + sp4[w][l][3];
                int tl = (t & 32) + l;
                float zz = sz[w][tl];
                float y = fmaf(su[w][tl], Dp, q) * (zz / (1.0f + __expf(-zz)));
                outp[t0 + tl] = y;
                __syncwarp();
            }
        }
    }
}

// ---- K7: transpose y [b][d][t] -> [m][k] bf16 hi/lo ----
__global__ void k_ytr()
{
    __shared__ float s[32][33];
    int t0 = blockIdx.x * 32, d0 = blockIdx.y * 32, b = blockIdx.z;
    int tx = threadIdx.x, ty = threadIdx.y;   // (32,8)
    for (int r = ty; r < 32; r += 8)
        s[r][tx] = g_ygT[((size_t)b * DI + d0 + r) * L_SEQ + t0 + tx];
    __syncthreads();
    for (int r = ty; r < 32; r += 8) {
        size_t m = (size_t)b * L_SEQ + t0 + r;
        float v = s[tx][r];
        bf16 h, l; split_bf16(v, h, l);
        g_y_hi[m * DI + d0 + tx] = h;
        g_y_lo[m * DI + d0 + tx] = l;
    }
}

// ---- K8: final LN on both halves + residual ----
__global__ void k_final(const float* __restrict__ x,
                        const float* __restrict__ w,
                        const float* __restrict__ b,
                        float* __restrict__ out)
{
    int row = blockIdx.x * 8 + (threadIdx.x >> 5);
    int l   = threadIdx.x & 31;
    int bi = row >> 12, ij = row & 4095;
    size_t m1 = (size_t)row;
    size_t m2 = (size_t)(4 + bi) * L_SEQ + ((ij & 63) << 6) + (ij >> 6);

    float ww[8], bb[8], a[8], c[8], xv[8];
    *(float4*)(ww)     = *(const float4*)(w + l * 8);
    *(float4*)(ww + 4) = *(const float4*)(w + l * 8 + 4);
    *(float4*)(bb)     = *(const float4*)(b + l * 8);
    *(float4*)(bb + 4) = *(const float4*)(b + l * 8 + 4);
    const float* p1 = g_ym + m1 * DMODEL + l * 8;
    const float* p2 = g_ym + m2 * DMODEL + l * 8;
    *(float4*)(a)     = *(const float4*)(p1);
    *(float4*)(a + 4) = *(const float4*)(p1 + 4);
    *(float4*)(c)     = *(const float4*)(p2);
    *(float4*)(c + 4) = *(const float4*)(p2 + 4);
    const float* xr = x + m1 * DMODEL + l * 8;
    *(float4*)(xv)     = *(const float4*)(xr);
    *(float4*)(xv + 4) = *(const float4*)(xr + 4);

    float s1 = 0.f, q1 = 0.f, s2 = 0.f, q2 = 0.f;
#pragma unroll
    for (int i = 0; i < 8; i++) {
        s1 += a[i]; q1 += a[i] * a[i];
        s2 += c[i]; q2 += c[i] * c[i];
    }
    s1 = warp_sum(s1); q1 = warp_sum(q1);
    s2 = warp_sum(s2); q2 = warp_sum(q2);
    float mu1 = s1 * (1.0f / DMODEL);
    float rs1 = rsqrtf(q1 * (1.0f / DMODEL) - mu1 * mu1 + 1e-6f);
    float mu2 = s2 * (1.0f / DMODEL);
    float rs2 = rsqrtf(q2 * (1.0f / DMODEL) - mu2 * mu2 + 1e-6f);

    float o[8];
#pragma unroll
    for (int i = 0; i < 8; i++)
        o[i] = xv[i] + ((a[i] - mu1) * rs1 * ww[i] + bb[i])
                     + ((c[i] - mu2) * rs2 * ww[i] + bb[i]);
    float* op = out + m1 * DMODEL + l * 8;
    *(float4*)(op)     = *(float4*)(o);
    *(float4*)(op + 4) = *(float4*)(o + 4);
}

extern "C" void kernel_launch(void* const* d_in, const int* in_sizes, int n_in,
                              void* d_out, int out_size)
{
    const float* x      = (const float*)d_in[0];
    const float* ln1_w  = (const float*)d_in[1];
    const float* ln1_b  = (const float*)d_in[2];
    const float* ln2_w  = (const float*)d_in[3];
    const float* ln2_b  = (const float*)d_in[4];
    const float* W_in   = (const float*)d_in[5];
    const float* conv_w = (const float*)d_in[6];
    const float* conv_b = (const float*)d_in[7];
    const float* W_x    = (const float*)d_in[8];
    const float* W_dt   = (const float*)d_in[9];
    const float* b_dt   = (const float*)d_in[10];
    const float* A_log  = (const float*)d_in[11];
    const float* D_par  = (const float*)d_in[12];
    const float* W_out  = (const float*)d_in[13];
    float* out = (float*)d_out;

    cudaFuncSetAttribute(tg<0>, cudaFuncAttributeMaxDynamicSharedMemorySize, 65536);
    cudaFuncSetAttribute(tg<1>, cudaFuncAttributeMaxDynamicSharedMemorySize, 65536);
    cudaFuncSetAttribute(tg<2>, cudaFuncAttributeMaxDynamicSharedMemorySize, 65536);

    k_ln_dup<<<2048, 256>>>(x, ln1_w, ln1_b);
    k_cvt<<<1024, 256>>>(W_in,  0, 1024 * 256, 1024 * 256);
    k_cvt<<<512,  256>>>(W_x,   1, 144 * 512,  256 * 512);
    k_cvt<<<512,  256>>>(W_out, 2, 256 * 512,  256 * 512);
    tg<0><<<dim3(8, 256), 256, 65536>>>();
    k_conv<<<65536, 256>>>(conv_w, conv_b);
    tg<1><<<dim3(2, 256), 256, 65536>>>();
    k_dt<<<2048, 256>>>(W_dt, b_dt);
    k_scan<<<dim3(64, 8), 256>>>(A_log, D_par);
    k_ytr<<<dim3(128, 16, 8), dim3(32, 8)>>>();
    tg<2><<<dim3(2, 256), 256, 65536>>>();
    k_final<<<2048, 256>>>(x, ln2_w, ln2_b, out);
}

// round 13
// speedup vs baseline: 1.5067x; 1.0366x over previous
#include <cuda_runtime.h>
#include <cuda_bf16.h>
#include <cstdint>
#include <math.h>

#define L_SEQ   4096
#define DMODEL  256
#define DI      512
#define M_TOT   32768
#define M_HALF  16384
#define NDBL    144

typedef __nv_bfloat16 bf16;

// ---------------- scratch ----------------
__device__ bf16  g_xm_hi [(size_t)M_HALF * DMODEL];
__device__ bf16  g_xm_lo [(size_t)M_HALF * DMODEL];
__device__ float g_xpre  [(size_t)M_HALF * DI];      // dir-1 rows only
__device__ float g_z     [(size_t)M_HALF * DI];      // dir-1 rows only
__device__ float g_xc    [(size_t)M_TOT * DI];
__device__ bf16  g_xc_hi [(size_t)M_TOT * DI];
__device__ bf16  g_xc_lo [(size_t)M_TOT * DI];
__device__ float g_xdbl  [(size_t)M_TOT * NDBL];
__device__ float g_dt    [(size_t)M_TOT * DI];
__device__ float g_ygT   [(size_t)8 * DI * L_SEQ];   // [b][d][t]
__device__ bf16  g_y_hi  [(size_t)M_TOT * DI];       // [m][k]
__device__ bf16  g_y_lo  [(size_t)M_TOT * DI];
__device__ float g_ym    [(size_t)M_TOT * DMODEL];
// weights split to bf16 hi/lo (W_x padded 144 -> 256 rows of zeros)
__device__ bf16  g_wi_hi [1024 * 256];
__device__ bf16  g_wi_lo [1024 * 256];
__device__ bf16  g_wx_hi [256 * 512];
__device__ bf16  g_wx_lo [256 * 512];
__device__ bf16  g_wo_hi [256 * 512];
__device__ bf16  g_wo_lo [256 * 512];

// ---------------- helpers ----------------
__device__ __forceinline__ uint32_t smem_u32(const void* p) {
    uint32_t a;
    asm("{ .reg .u64 t; cvta.to.shared.u64 t, %1; cvt.u32.u64 %0, t; }" : "=r"(a) : "l"(p));
    return a;
}
__device__ __forceinline__ float warp_sum(float v) {
#pragma unroll
    for (int o = 16; o > 0; o >>= 1) v += __shfl_xor_sync(0xffffffffu, v, o);
    return v;
}
__device__ __forceinline__ void split_bf16(float v, bf16& h, bf16& l) {
    h = __float2bfloat16(v);
    l = __float2bfloat16(v - __bfloat162float(h));
}

#define LDSM4(d0, d1, d2, d3, a) \
    asm volatile("ldmatrix.sync.aligned.m8n8.x4.shared.b16 {%0,%1,%2,%3}, [%4];" \
                 : "=r"(d0), "=r"(d1), "=r"(d2), "=r"(d3) : "r"(a))
#define MMA16816(d, a, b0, b1) \
    asm volatile("mma.sync.aligned.m16n8k16.row.col.f32.bf16.bf16.f32 " \
                 "{%0,%1,%2,%3}, {%4,%5,%6,%7}, {%8,%9}, {%0,%1,%2,%3};" \
                 : "+f"((d)[0]), "+f"((d)[1]), "+f"((d)[2]), "+f"((d)[3]) \
                 : "r"((a)[0]), "r"((a)[1]), "r"((a)[2]), "r"((a)[3]), "r"(b0), "r"(b1))
#define CPA(dst, src) \
    asm volatile("cp.async.cg.shared.global [%0], [%1], 16;" :: "r"(dst), "l"(src))
#define CP_COMMIT() asm volatile("cp.async.commit_group;" ::: "memory")
#define CP_WAIT1()  asm volatile("cp.async.wait_group 1;" ::: "memory")
#define CP_WAIT0()  asm volatile("cp.async.wait_group 0;" ::: "memory")

// ---- K1: LN1 -> bf16 hi/lo, dir-1 layout only ----
__global__ void k_ln_dup(const float* __restrict__ x,
                         const float* __restrict__ w,
                         const float* __restrict__ b)
{
    int row = blockIdx.x * 8 + (threadIdx.x >> 5);
    int l   = threadIdx.x & 31;
    float a[8], ww[8], bb[8];
    const float* xr = x + (size_t)row * DMODEL + l * 8;
    *(float4*)(a)     = *(const float4*)(xr);
    *(float4*)(a + 4) = *(const float4*)(xr + 4);
    *(float4*)(ww)     = *(const float4*)(w + l * 8);
    *(float4*)(ww + 4) = *(const float4*)(w + l * 8 + 4);
    *(float4*)(bb)     = *(const float4*)(b + l * 8);
    *(float4*)(bb + 4) = *(const float4*)(b + l * 8 + 4);
    float s = 0.f, q = 0.f;
#pragma unroll
    for (int i = 0; i < 8; i++) { s += a[i]; q += a[i] * a[i]; }
    s = warp_sum(s); q = warp_sum(q);
    float mu = s * (1.0f / DMODEL);
    float rs = rsqrtf(q * (1.0f / DMODEL) - mu * mu + 1e-6f);
    bf16 oh[8], ol[8];
#pragma unroll
    for (int i = 0; i < 8; i++) {
        float o = (a[i] - mu) * rs * ww[i] + bb[i];
        split_bf16(o, oh[i], ol[i]);
    }
    *(uint4*)(g_xm_hi + (size_t)row * DMODEL + l * 8) = *(uint4*)oh;
    *(uint4*)(g_xm_lo + (size_t)row * DMODEL + l * 8) = *(uint4*)ol;
}

// ---- weight split converter (mode selects destination symbol; pads with zeros) ----
__global__ void k_cvt(const float* __restrict__ s, int mode, int nsrc, int ntot)
{
    int i = blockIdx.x * 256 + threadIdx.x;
    if (i >= ntot) return;
    bf16* hi = (mode == 0) ? g_wi_hi : (mode == 1) ? g_wx_hi : g_wo_hi;
    bf16* lo = (mode == 0) ? g_wi_lo : (mode == 1) ? g_wx_lo : g_wo_lo;
    if (i < nsrc) {
        split_bf16(s[i], hi[i], lo[i]);
    } else {
        hi[i] = __float2bfloat16(0.f);
        lo[i] = __float2bfloat16(0.f);
    }
}

// ---------------- HMMA GEMM: C[M,N] = A[M,K] * W[N,K]^T, split bf16 ----------------
// 2-stage cp.async double-buffered pipeline. Dynamic smem: 2 stages x (A 16KB + B 16KB) = 64KB.
// MODE 0: A=g_xm (K=256), N=1024, grid(8,128)  -> split g_xpre/g_z (dir-1 rows only)
// MODE 1: A=g_xc (K=512), N=256 (padded), grid(2,256) -> g_xdbl (n<144)
// MODE 2: A=g_y  (K=512), N=256, grid(2,256)  -> g_ym
template<int MODE>
__global__ void __launch_bounds__(256, 2) tg()
{
    constexpr int K   = (MODE == 0) ? 256 : 512;
    constexpr int NKC = K / 32;

    extern __shared__ bf16 smem[];

    const bf16* __restrict__ Ahi = (MODE == 0) ? g_xm_hi : (MODE == 1) ? g_xc_hi : g_y_hi;
    const bf16* __restrict__ Alo = (MODE == 0) ? g_xm_lo : (MODE == 1) ? g_xc_lo : g_y_lo;
    const bf16* __restrict__ Bhi = (MODE == 0) ? g_wi_hi : (MODE == 1) ? g_wx_hi : g_wo_hi;
    const bf16* __restrict__ Blo = (MODE == 0) ? g_wi_lo : (MODE == 1) ? g_wx_lo : g_wo_lo;

    int tid = threadIdx.x, w = tid >> 5, lane = tid & 31;
    int m0 = blockIdx.y * 128, n0 = blockIdx.x * 128;
    int wm = (w >> 2) * 64, wn = (w & 3) * 32;

    float acc[4][4][4] = {};

    uint32_t sbase = smem_u32(smem);

    // loader indices: 4 x (A 16B + B 16B) per thread per stage
    int lrow[4], lch[4];
#pragma unroll
    for (int j = 0; j < 4; j++) {
        int i = tid + 256 * j;
        lrow[j] = i >> 3;
        lch[j]  = i & 7;
    }

#define LOADS(s, kc) { \
    uint32_t abase = sbase + (uint32_t)(s) * 32768u; \
    _Pragma("unroll") \
    for (int j = 0; j < 4; j++) { \
        const bf16* asrc = (lch[j] < 4 ? Ahi : Alo) + (size_t)(m0 + lrow[j]) * K + (kc) * 32 + (lch[j] & 3) * 8; \
        const bf16* bsrc = (lch[j] < 4 ? Bhi : Blo) + (size_t)(n0 + lrow[j]) * K + (kc) * 32 + (lch[j] & 3) * 8; \
        uint32_t off = 2u * (uint32_t)(lrow[j] * 64 + ((lch[j] ^ (lrow[j] & 7)) << 3)); \
        CPA(abase + off, asrc); \
        CPA(abase + 16384u + off, bsrc); \
    } }

    LOADS(0, 0); CP_COMMIT();

    int q8 = lane >> 3, r8 = lane & 7;

    for (int kc = 0; kc < NKC; kc++) {
        int cur = kc & 1;
        if (kc + 1 < NKC) {
            LOADS(cur ^ 1, kc + 1); CP_COMMIT();
            CP_WAIT1();
        } else {
            CP_WAIT0();
        }
        __syncthreads();

        uint32_t sAu = sbase + (uint32_t)cur * 32768u;
        uint32_t sBu = sAu + 16384u;

#pragma unroll
        for (int ks = 0; ks < 2; ks++) {
            int ckh = ks * 2;        // hi chunks
            int ckl = 4 + ks * 2;    // lo chunks
            uint32_t ah[4][4], al[4][4], bh[2][4], bl[2][4];
#pragma unroll
            for (int mt = 0; mt < 4; mt++) {
                int row = wm + mt * 16 + ((q8 & 1) << 3) + r8;
                int c  = ckh + (q8 >> 1);
                uint32_t a1 = sAu + (row * 64 + ((c ^ (row & 7)) << 3)) * 2;
                LDSM4(ah[mt][0], ah[mt][1], ah[mt][2], ah[mt][3], a1);
                int c2 = ckl + (q8 >> 1);
                uint32_t a2 = sAu + (row * 64 + ((c2 ^ (row & 7)) << 3)) * 2;
                LDSM4(al[mt][0], al[mt][1], al[mt][2], al[mt][3], a2);
            }
#pragma unroll
            for (int p = 0; p < 2; p++) {
                int row = wn + p * 16 + ((q8 >> 1) << 3) + r8;
                int c  = ckh + (q8 & 1);
                uint32_t a1 = sBu + (row * 64 + ((c ^ (row & 7)) << 3)) * 2;
                LDSM4(bh[p][0], bh[p][1], bh[p][2], bh[p][3], a1);
                int c2 = ckl + (q8 & 1);
                uint32_t a2 = sBu + (row * 64 + ((c2 ^ (row & 7)) << 3)) * 2;
                LDSM4(bl[p][0], bl[p][1], bl[p][2], bl[p][3], a2);
            }
#pragma unroll
            for (int mt = 0; mt < 4; mt++) {
#pragma unroll
                for (int nt = 0; nt < 4; nt++) {
                    int p = nt >> 1, o = (nt & 1) << 1;
                    MMA16816(acc[mt][nt], ah[mt], bh[p][o], bh[p][o + 1]);   // hi*hi
                    MMA16816(acc[mt][nt], ah[mt], bl[p][o], bl[p][o + 1]);   // hi*lo
                    MMA16816(acc[mt][nt], al[mt], bh[p][o], bh[p][o + 1]);   // lo*hi
                }
            }
        }

        __syncthreads();
    }

    // ---- epilogue: direct register -> gmem ----
    int g = lane >> 2, qq = lane & 3;
#pragma unroll
    for (int mt = 0; mt < 4; mt++) {
#pragma unroll
        for (int nt = 0; nt < 4; nt++) {
            int col = n0 + wn + nt * 8 + qq * 2;
            size_t r0 = (size_t)m0 + wm + mt * 16 + g;
#pragma unroll
            for (int hrow = 0; hrow < 2; hrow++) {
                size_t m = r0 + hrow * 8;
                float2 v = make_float2(acc[mt][nt][hrow * 2], acc[mt][nt][hrow * 2 + 1]);
                if (MODE == 0) {
                    if (col < 512) *(float2*)&g_xpre[m * DI + col] = v;
                    else           *(float2*)&g_z   [m * DI + col - 512] = v;
                } else if (MODE == 1) {
                    if (col < NDBL) *(float2*)&g_xdbl[m * NDBL + col] = v;
                } else {
                    *(float2*)&g_ym[m * DMODEL + col] = v;
                }
            }
        }
    }
}

// ---- K3: depthwise causal conv(4) + SiLU (+ bf16 hi/lo for GEMM2) ----
// Source xpre/z stored for dir-1 rows only; dir-2 gathers through the transpose perm.
__global__ void k_conv(const float* __restrict__ cw, const float* __restrict__ cb)
{
    int idx = blockIdx.x * 256 + threadIdx.x;     // over M_TOT*DI
    int d = idx & (DI - 1);
    int m = idx >> 9;
    int t = m & (L_SEQ - 1);
    int b = m >> 12;                              // 0..7
    bool dir2 = (b >= 4);
    int bb = dir2 ? (b - 4) : b;
    size_t brow = (size_t)bb * L_SEQ;

    float acc = cb[d];
    float w0 = cw[d*4+0], w1 = cw[d*4+1], w2 = cw[d*4+2], w3 = cw[d*4+3];

#define SRC(tau) ((brow + (dir2 ? (size_t)((((tau) & 63) << 6) | ((tau) >> 6)) : (size_t)(tau))) * DI + d)
    if (t >= 3) {
        acc = fmaf(g_xpre[SRC(t - 3)], w0, acc);
        acc = fmaf(g_xpre[SRC(t - 2)], w1, acc);
        acc = fmaf(g_xpre[SRC(t - 1)], w2, acc);
    } else {
        if (t >= 2) acc = fmaf(g_xpre[SRC(t - 2)], w1, acc);
        if (t >= 1) acc = fmaf(g_xpre[SRC(t - 1)], w2, acc);
    }
    acc = fmaf(g_xpre[SRC(t)], w3, acc);
#undef SRC
    float v = acc / (1.0f + __expf(-acc));
    size_t base = (size_t)m * DI + d;
    g_xc[base] = v;
    bf16 h, l; split_bf16(v, h, l);
    g_xc_hi[base] = h;
    g_xc_lo[base] = l;
}

// ---- K5: dt projection (K=16) + softplus ----
__global__ void k_dt(const float* __restrict__ Wdt, const float* __restrict__ bdt)
{
    __shared__ float sW[16 * 512];
    __shared__ float sx[16][16];
    int m0 = blockIdx.x * 16;
    int tid = threadIdx.x;
    for (int i = tid; i < 8192; i += 256) {
        int dd = i >> 4, r = i & 15;
        sW[r * 512 + dd] = Wdt[i];
    }
    {
        int mi = tid >> 4, r = tid & 15;
        sx[mi][r] = g_xdbl[(size_t)(m0 + mi) * NDBL + r];
    }
    __syncthreads();
#pragma unroll
    for (int mi = 0; mi < 16; mi++) {
        for (int d = tid; d < 512; d += 256) {
            float acc = bdt[d];
#pragma unroll
            for (int r = 0; r < 16; r++) acc = fmaf(sx[mi][r], sW[r * 512 + d], acc);
            float sp = (acc > 20.f) ? acc : log1pf(__expf(acc));
            g_dt[(size_t)(m0 + mi) * DI + d] = sp;
        }
    }
}

// ---- K6: selective scan + u*D + silu(z) gate, write [b][d][t] ----
// z stored for dir-1 rows only; dir-2 (b>=4) gathers through the transpose perm.
__global__ void __launch_bounds__(256) k_scan(const float* __restrict__ A_log,
                                              const float* __restrict__ D_param)
{
    constexpr int CW = 8;
    int b  = blockIdx.y;
    int d0 = blockIdx.x * CW;
    int tid = threadIdx.x, w = tid >> 5, l = tid & 31;
    int d = d0 + w;

    __shared__ float sB[64][68];
    __shared__ float sC[64][68];
    __shared__ float sdt[CW][64];
    __shared__ float su [CW][64];
    __shared__ float sz [CW][64];
    __shared__ float sp4[CW][32][5];

    float A1 = -expf(A_log[d * 64 + l]);
    float A2 = -expf(A_log[d * 64 + 32 + l]);
    float Dp = D_param[d];
    float h1 = 0.f, h2 = 0.f;
    size_t mb = (size_t)b * L_SEQ;
    bool dir2 = (b >= 4);
    size_t zb = (size_t)(dir2 ? (b - 4) : b) * L_SEQ;
    float* outp = g_ygT + ((size_t)b * DI + d) * L_SEQ;

    for (int t0 = 0; t0 < L_SEQ; t0 += 64) {
        __syncthreads();
        for (int i = tid; i < 64 * 32; i += 256) {
            int row = i >> 5, c4 = (i & 31) << 2;
            float4 v = *(const float4*)&g_xdbl[(mb + t0 + row) * NDBL + 16 + c4];
            if (c4 < 64) *(float4*)&sB[row][c4] = v;
            else         *(float4*)&sC[row][c4 - 64] = v;
        }
        for (int i = tid; i < CW * 64; i += 256) {
            int t = i >> 3, ch = i & 7;
            int tt = t0 + t;
            size_t g = (mb + tt) * DI + d0 + ch;
            sdt[ch][t] = g_dt[g];
            su [ch][t] = g_xc[g];
            size_t zr = zb + (dir2 ? (size_t)(((tt & 63) << 6) | (tt >> 6)) : (size_t)tt);
            sz [ch][t] = g_z[zr * DI + d0 + ch];
        }
        __syncthreads();

#pragma unroll 4
        for (int t = 0; t < 64; t++) {
            float dtv = sdt[w][t];
            float xx  = dtv * su[w][t];
            float a1 = __expf(dtv * A1);
            float a2 = __expf(dtv * A2);
            h1 = fmaf(a1, h1, xx * sB[t][l]);
            h2 = fmaf(a2, h2, xx * sB[t][l + 32]);
            float p = fmaf(h2, sC[t][l + 32], h1 * sC[t][l]);
            p += __shfl_xor_sync(0xffffffffu, p, 16);
            p += __shfl_xor_sync(0xffffffffu, p, 8);
            p += __shfl_xor_sync(0xffffffffu, p, 4);
            if (l < 4) sp4[w][t & 31][l] = p;
            if ((t & 31) == 31) {
                __syncwarp();
                float q = sp4[w][l][0] + sp4[w][l][1] + sp4[w][l][2] + sp4[w][l][3];
                int tl = (t & 32) + l;
                float zz = sz[w][tl];
                float y = fmaf(su[w][tl], Dp, q) * (zz / (1.0f + __expf(-zz)));
                outp[t0 + tl] = y;
                __syncwarp();
            }
        }
    }
}

// ---- K7: transpose y [b][d][t] -> [m][k] bf16 hi/lo ----
__global__ void k_ytr()
{
    __shared__ float s[32][33];
    int t0 = blockIdx.x * 32, d0 = blockIdx.y * 32, b = blockIdx.z;
    int tx = threadIdx.x, ty = threadIdx.y;   // (32,8)
    for (int r = ty; r < 32; r += 8)
        s[r][tx] = g_ygT[((size_t)b * DI + d0 + r) * L_SEQ + t0 + tx];
    __syncthreads();
    for (int r = ty; r < 32; r += 8) {
        size_t m = (size_t)b * L_SEQ + t0 + r;
        float v = s[tx][r];
        bf16 h, l; split_bf16(v, h, l);
        g_y_hi[m * DI + d0 + tx] = h;
        g_y_lo[m * DI + d0 + tx] = l;
    }
}

// ---- K8: final LN on both halves + residual ----
__global__ void k_final(const float* __restrict__ x,
                        const float* __restrict__ w,
                        const float* __restrict__ b,
                        float* __restrict__ out)
{
    int row = blockIdx.x * 8 + (threadIdx.x >> 5);
    int l   = threadIdx.x & 31;
    int bi = row >> 12, ij = row & 4095;
    size_t m1 = (size_t)row;
    size_t m2 = (size_t)(4 + bi) * L_SEQ + ((ij & 63) << 6) + (ij >> 6);

    float ww[8], bb[8], a[8], c[8], xv[8];
    *(float4*)(ww)     = *(const float4*)(w + l * 8);
    *(float4*)(ww + 4) = *(const float4*)(w + l * 8 + 4);
    *(float4*)(bb)     = *(const float4*)(b + l * 8);
    *(float4*)(bb + 4) = *(const float4*)(b + l * 8 + 4);
    const float* p1 = g_ym + m1 * DMODEL + l * 8;
    const float* p2 = g_ym + m2 * DMODEL + l * 8;
    *(float4*)(a)     = *(const float4*)(p1);
    *(float4*)(a + 4) = *(const float4*)(p1 + 4);
    *(float4*)(c)     = *(const float4*)(p2);
    *(float4*)(c + 4) = *(const float4*)(p2 + 4);
    const float* xr = x + m1 * DMODEL + l * 8;
    *(float4*)(xv)     = *(const float4*)(xr);
    *(float4*)(xv + 4) = *(const float4*)(xr + 4);

    float s1 = 0.f, q1 = 0.f, s2 = 0.f, q2 = 0.f;
#pragma unroll
    for (int i = 0; i < 8; i++) {
        s1 += a[i]; q1 += a[i] * a[i];
        s2 += c[i]; q2 += c[i] * c[i];
    }
    s1 = warp_sum(s1); q1 = warp_sum(q1);
    s2 = warp_sum(s2); q2 = warp_sum(q2);
    float mu1 = s1 * (1.0f / DMODEL);
    float rs1 = rsqrtf(q1 * (1.0f / DMODEL) - mu1 * mu1 + 1e-6f);
    float mu2 = s2 * (1.0f / DMODEL);
    float rs2 = rsqrtf(q2 * (1.0f / DMODEL) - mu2 * mu2 + 1e-6f);

    float o[8];
#pragma unroll
    for (int i = 0; i < 8; i++)
        o[i] = xv[i] + ((a[i] - mu1) * rs1 * ww[i] + bb[i])
                     + ((c[i] - mu2) * rs2 * ww[i] + bb[i]);
    float* op = out + m1 * DMODEL + l * 8;
    *(float4*)(op)     = *(float4*)(o);
    *(float4*)(op + 4) = *(float4*)(o + 4);
}

extern "C" void kernel_launch(void* const* d_in, const int* in_sizes, int n_in,
                              void* d_out, int out_size)
{
    const float* x      = (const float*)d_in[0];
    const float* ln1_w  = (const float*)d_in[1];
    const float* ln1_b  = (const float*)d_in[2];
    const float* ln2_w  = (const float*)d_in[3];
    const float* ln2_b  = (const float*)d_in[4];
    const float* W_in   = (const float*)d_in[5];
    const float* conv_w = (const float*)d_in[6];
    const float* conv_b = (const float*)d_in[7];
    const float* W_x    = (const float*)d_in[8];
    const float* W_dt   = (const float*)d_in[9];
    const float* b_dt   = (const float*)d_in[10];
    const float* A_log  = (const float*)d_in[11];
    const float* D_par  = (const float*)d_in[12];
    const float* W_out  = (const float*)d_in[13];
    float* out = (float*)d_out;

    cudaFuncSetAttribute(tg<0>, cudaFuncAttributeMaxDynamicSharedMemorySize, 65536);
    cudaFuncSetAttribute(tg<1>, cudaFuncAttributeMaxDynamicSharedMemorySize, 65536);
    cudaFuncSetAttribute(tg<2>, cudaFuncAttributeMaxDynamicSharedMemorySize, 65536);

    k_ln_dup<<<2048, 256>>>(x, ln1_w, ln1_b);
    k_cvt<<<1024, 256>>>(W_in,  0, 1024 * 256, 1024 * 256);
    k_cvt<<<512,  256>>>(W_x,   1, 144 * 512,  256 * 512);
    k_cvt<<<512,  256>>>(W_out, 2, 256 * 512,  256 * 512);
    tg<0><<<dim3(8, 128), 256, 65536>>>();
    k_conv<<<65536, 256>>>(conv_w, conv_b);
    tg<1><<<dim3(2, 256), 256, 65536>>>();
    k_dt<<<2048, 256>>>(W_dt, b_dt);
    k_scan<<<dim3(64, 8), 256>>>(A_log, D_par);
    k_ytr<<<dim3(128, 16, 8), dim3(32, 8)>>>();
    tg<2><<<dim3(2, 256), 256, 65536>>>();
    k_final<<<2048, 256>>>(x, ln2_w, ln2_b, out);
}